// round 15
// baseline (speedup 1.0000x reference)
#include <cuda_runtime.h>
#include <cuda_fp16.h>
#include <cstdint>

#define N_NODES 50000
#define N_EDGES 800000
#define FDIM    128
#define HDIM    128
#define TDIM    10
#define NB      ((N_NODES + 255) / 256)    // 196 scan blocks

// Scratch (device globals) — only ever referenced from DEVICE code.
__device__ __align__(16) float g_dinv[N_NODES];
__device__ int  g_cnt[N_NODES];
__device__ int  g_rowptr[N_NODES];
__device__ int  g_cursor[N_NODES];
__device__ int  g_blocksum[NB];
__device__ int  g_blockoff[NB];
__device__ __align__(16) int2   g_edges[N_EDGES];
// fp16 A-side data path
__device__ __align__(16) __half g_x16[N_NODES * FDIM];
__device__ __align__(16) __half g_T1h[N_NODES * FDIM];
__device__ __align__(16) __half g_T2h[N_NODES * FDIM];   // P = L_hat @ T1
// fp16 B, TRANSPOSED [n=256][k=384], weight-folded:
//   k<128: W0-W2 ; 128<=k<256: W1 ; k>=256: 2*W2   (n<128: z | n>=128: h)
__device__ __align__(16) __half g_Bt[256 * 384];

// ---------------------------------------------------------------------------
// Stage 0a: weight fold -> fp16 transposed B + init (one launch)
// ---------------------------------------------------------------------------
__global__ void split_kernel(const float* __restrict__ Wz,
                             const float* __restrict__ Wh) {
    int idx = blockIdx.x * blockDim.x + threadIdx.x;
    if (idx < N_NODES) { g_dinv[idx] = 0.f; g_cnt[idx] = 0; }
    if (idx < 256 * 384) {
        int n = idx / 384;
        int k = idx % 384;
        const float* W = (n < 128) ? Wz : Wh;
        int cc = n & 127;
        float v;
        if (k < 128)      v = W[k * 128 + cc] - W[(k + 256) * 128 + cc];  // W0 - W2
        else if (k < 256) v = W[k * 128 + cc];                            // W1
        else              v = 2.f * W[k * 128 + cc];                      // 2*W2
        g_Bt[idx] = __float2half_rn(v);
    }
}

// Stage 0b: x -> fp16 copy
__global__ void cvtx_kernel(const float* __restrict__ x) {
    int i = blockIdx.x * blockDim.x + threadIdx.x;
    if (i < N_NODES * FDIM / 4) {
        float4 v = ((const float4*)x)[i];
        __half2 lo = __floats2half2_rn(v.x, v.y);
        __half2 hi = __floats2half2_rn(v.z, v.w);
        uint2 o;
        o.x = *reinterpret_cast<uint32_t*>(&lo);
        o.y = *reinterpret_cast<uint32_t*>(&hi);
        ((uint2*)g_x16)[i] = o;
    }
}

// Stage 1: deg[src] += w ; cnt[dst] += 1        (edge_index is int32)
__global__ void deg_kernel(const int* __restrict__ ei,
                           const float* __restrict__ ew) {
    int e = blockIdx.x * blockDim.x + threadIdx.x;
    if (e < N_EDGES) {
        atomicAdd(&g_dinv[ei[e]], ew[e]);
        atomicAdd(&g_cnt[ei[N_EDGES + e]], 1);
    }
}

// ---------------------------------------------------------------------------
// Stage 2: grid-wide 3-phase exclusive scan
// ---------------------------------------------------------------------------
__global__ void blocksum_kernel() {
    int i = blockIdx.x * 256 + threadIdx.x;
    int v = 0;
    if (i < N_NODES) {
        v = g_cnt[i];
        float d = g_dinv[i];
        g_dinv[i] = (d > 0.f) ? rsqrtf(d) : 0.f;
    }
    __shared__ int ws[8];
    int lane = threadIdx.x & 31, wid = threadIdx.x >> 5;
#pragma unroll
    for (int o = 16; o > 0; o >>= 1) v += __shfl_down_sync(0xffffffffu, v, o);
    if (lane == 0) ws[wid] = v;
    __syncthreads();
    if (threadIdx.x == 0) {
        int s = 0;
#pragma unroll
        for (int w = 0; w < 8; w++) s += ws[w];
        g_blocksum[blockIdx.x] = s;
    }
}

__global__ void blockscan_kernel() {
    __shared__ int ws[8];
    int tid = threadIdx.x, lane = tid & 31, wid = tid >> 5;
    int v = (tid < NB) ? g_blocksum[tid] : 0;
    int inc = v;
#pragma unroll
    for (int o = 1; o < 32; o <<= 1) {
        int t = __shfl_up_sync(0xffffffffu, inc, o);
        if (lane >= o) inc += t;
    }
    if (lane == 31) ws[wid] = inc;
    __syncthreads();
    if (wid == 0 && lane < 8) {
        int t = ws[lane];
#pragma unroll
        for (int o = 1; o < 8; o <<= 1) {
            int u = __shfl_up_sync(0xffu, t, o);
            if (lane >= o) t += u;
        }
        ws[lane] = t;
    }
    __syncthreads();
    int excl = inc - v + ((wid > 0) ? ws[wid - 1] : 0);
    if (tid < NB) g_blockoff[tid] = excl;
}

__global__ void rowptr_kernel() {
    int i = blockIdx.x * 256 + threadIdx.x;
    int v = (i < N_NODES) ? g_cnt[i] : 0;
    __shared__ int ws[8];
    int lane = threadIdx.x & 31, wid = threadIdx.x >> 5;
    int inc = v;
#pragma unroll
    for (int o = 1; o < 32; o <<= 1) {
        int t = __shfl_up_sync(0xffffffffu, inc, o);
        if (lane >= o) inc += t;
    }
    if (lane == 31) ws[wid] = inc;
    __syncthreads();
    if (wid == 0 && lane < 8) {
        int t = ws[lane];
#pragma unroll
        for (int o = 1; o < 8; o <<= 1) {
            int u = __shfl_up_sync(0xffu, t, o);
            if (lane >= o) t += u;
        }
        ws[lane] = t;
    }
    __syncthreads();
    int excl = inc - v + ((wid > 0) ? ws[wid - 1] : 0) + g_blockoff[blockIdx.x];
    if (i < N_NODES) { g_rowptr[i] = excl; g_cursor[i] = excl; }
}

// Stage 3: scatter packed (src, norm) into dst-grouped CSR slots
__global__ void scatter_kernel(const int* __restrict__ ei,
                               const float* __restrict__ ew) {
    int e = blockIdx.x * blockDim.x + threadIdx.x;
    if (e < N_EDGES) {
        int s = ei[e];
        int d = ei[N_EDGES + e];
        float nrm = -g_dinv[s] * ew[e] * g_dinv[d];
        int pos = atomicAdd(&g_cursor[d], 1);
        g_edges[pos] = make_int2(s, __float_as_int(nrm));
    }
}

// ---------------------------------------------------------------------------
// Stage 4/5: gather-side propagation (fp16 rows), HALF-WARP (16 lanes) per
// dst node: each lane holds 8 halves (16 B) -> one LDG.128 per edge per lane.
// ---------------------------------------------------------------------------
struct f8acc { float4 a, b; };

__device__ __forceinline__ void fma_h8(f8acc& acc, float w, uint4 r) {
    __half2 h0 = *reinterpret_cast<__half2*>(&r.x);
    __half2 h1 = *reinterpret_cast<__half2*>(&r.y);
    __half2 h2 = *reinterpret_cast<__half2*>(&r.z);
    __half2 h3 = *reinterpret_cast<__half2*>(&r.w);
    float2 f0 = __half22float2(h0);
    float2 f1 = __half22float2(h1);
    float2 f2 = __half22float2(h2);
    float2 f3 = __half22float2(h3);
    acc.a.x += w * f0.x; acc.a.y += w * f0.y;
    acc.a.z += w * f1.x; acc.a.w += w * f1.y;
    acc.b.x += w * f2.x; acc.b.y += w * f2.y;
    acc.b.z += w * f3.x; acc.b.w += w * f3.y;
}

__device__ __forceinline__ void store_h8(__half* dst, const f8acc& acc) {
    __half2 o0 = __floats2half2_rn(acc.a.x, acc.a.y);
    __half2 o1 = __floats2half2_rn(acc.a.z, acc.a.w);
    __half2 o2 = __floats2half2_rn(acc.b.x, acc.b.y);
    __half2 o3 = __floats2half2_rn(acc.b.z, acc.b.w);
    uint4 o;
    o.x = *reinterpret_cast<uint32_t*>(&o0);
    o.y = *reinterpret_cast<uint32_t*>(&o1);
    o.z = *reinterpret_cast<uint32_t*>(&o2);
    o.w = *reinterpret_cast<uint32_t*>(&o3);
    *reinterpret_cast<uint4*>(dst) = o;
}

__device__ __forceinline__ f8acc prop_gather16(const __half* __restrict__ in,
                                               int base, int cnt, int l16) {
    f8acc acc;
    acc.a = make_float4(0.f, 0.f, 0.f, 0.f);
    acc.b = make_float4(0.f, 0.f, 0.f, 0.f);
    int j = 0;
    for (; j + 4 <= cnt; j += 4) {
        int2 e0 = g_edges[base + j];
        int2 e1 = g_edges[base + j + 1];
        int2 e2 = g_edges[base + j + 2];
        int2 e3 = g_edges[base + j + 3];
        uint4 r0 = *(const uint4*)(in + (size_t)e0.x * FDIM + l16 * 8);
        uint4 r1 = *(const uint4*)(in + (size_t)e1.x * FDIM + l16 * 8);
        uint4 r2 = *(const uint4*)(in + (size_t)e2.x * FDIM + l16 * 8);
        uint4 r3 = *(const uint4*)(in + (size_t)e3.x * FDIM + l16 * 8);
        fma_h8(acc, __int_as_float(e0.y), r0);
        fma_h8(acc, __int_as_float(e1.y), r1);
        fma_h8(acc, __int_as_float(e2.y), r2);
        fma_h8(acc, __int_as_float(e3.y), r3);
    }
    for (; j < cnt; j++) {
        int2 e0 = g_edges[base + j];
        uint4 r0 = *(const uint4*)(in + (size_t)e0.x * FDIM + l16 * 8);
        fma_h8(acc, __int_as_float(e0.y), r0);
    }
    return acc;
}

__global__ void prop1_csr_kernel() {
    int node = (blockIdx.x * blockDim.x + threadIdx.x) >> 4;
    int l16  = threadIdx.x & 15;
    if (node >= N_NODES) return;
    f8acc acc = prop_gather16(g_x16, g_rowptr[node], g_cnt[node], l16);
    store_h8(g_T1h + (size_t)node * FDIM + l16 * 8, acc);
}

__global__ void prop2_csr_kernel() {
    int node = (blockIdx.x * blockDim.x + threadIdx.x) >> 4;
    int l16  = threadIdx.x & 15;
    if (node >= N_NODES) return;
    f8acc acc = prop_gather16(g_T1h, g_rowptr[node], g_cnt[node], l16);
    store_h8(g_T2h + (size_t)node * FDIM + l16 * 8, acc);
}

// ---------------------------------------------------------------------------
// Stage 6: fused GEMM (pure fp16 MMA m16n8k16, fp32 accum) + gate + proj
//   BM=64, BN=256 (128 z | 128 h), BK=16, 8 warps = 4M x 2N
// ---------------------------------------------------------------------------
#define BMF       64
#define BKT       16
#define NKB       24
#define A_HSTRIDE 20                        // halves per A smem row (40 B)
#define A_BYTES   (BMF * A_HSTRIDE * 2)     // 2560
#define B_HSTRIDE 24                        // halves per B smem row (48 B)
#define B_BYTES   (256 * B_HSTRIDE * 2)     // 12288
#define STG_BYTES (A_BYTES + B_BYTES)       // 14848
#define HN_STRIDE 132
#define EPI_BYTES ((BMF * HN_STRIDE + TDIM * HDIM) * 4)   // 38912
#define SMEM_BYTES ((2 * STG_BYTES) > EPI_BYTES ? (2 * STG_BYTES) : EPI_BYTES)

extern __shared__ float smem[];

__device__ __forceinline__ void cp_async16(uint32_t saddr, const void* g, int bytes) {
    asm volatile("cp.async.cg.shared.global [%0], [%1], 16, %2;"
                 :: "r"(saddr), "l"(g), "r"(bytes) : "memory");
}
__device__ __forceinline__ void cp_async8(uint32_t saddr, const void* g, int bytes) {
    asm volatile("cp.async.ca.shared.global [%0], [%1], 8, %2;"
                 :: "r"(saddr), "l"(g), "r"(bytes) : "memory");
}

__device__ __forceinline__ void mma_f16(float* c, const uint32_t* a, const uint32_t* b) {
    asm volatile(
        "mma.sync.aligned.m16n8k16.row.col.f32.f16.f16.f32 "
        "{%0,%1,%2,%3}, {%4,%5,%6,%7}, {%8,%9}, {%0,%1,%2,%3};"
        : "+f"(c[0]), "+f"(c[1]), "+f"(c[2]), "+f"(c[3])
        : "r"(a[0]), "r"(a[1]), "r"(a[2]), "r"(a[3]),
          "r"(b[0]), "r"(b[1]));
}

__device__ __forceinline__ float gate_fn(float z, float h) {
    float sig = 1.f / (1.f + __expf(-z));
    return (1.f - sig) * tanhf(h);
}

__global__ __launch_bounds__(256, 2) void fused_kernel(
    const float* __restrict__ bz0, const float* __restrict__ bz1,
    const float* __restrict__ bh0, const float* __restrict__ bh1,
    const float* __restrict__ Wlin, const float* __restrict__ blin,
    float* __restrict__ out)
{
    const int tid  = threadIdx.x;
    const int lane = tid & 31;
    const int wid  = tid >> 5;
    const int wm   = wid & 3;          // 4 M-blocks of 16
    const int wn   = wid >> 2;         // 2 N-groups of 64
    const int mwb  = wm * 16;
    const int m0   = blockIdx.x * BMF;

    const uint32_t smem_u32 = (uint32_t)__cvta_generic_to_shared(smem);

    float c[16][4];
#pragma unroll
    for (int ni = 0; ni < 16; ni++)
#pragma unroll
        for (int q = 0; q < 4; q++) c[ni][q] = 0.f;

    auto load_stage = [&](int kb, int s) {
        const int col = kb * BKT;
        const __half* Asrc;
        int c0;
        if (col < 128)      { Asrc = g_x16; c0 = col; }
        else if (col < 256) { Asrc = g_T1h; c0 = col - 128; }
        else                { Asrc = g_T2h; c0 = col - 256; }

        uint32_t sa = smem_u32 + (uint32_t)(s * STG_BYTES);
        uint32_t sb = sa + A_BYTES;

        {
            int m  = tid >> 2;
            int c4 = (tid & 3) * 4;
            int node  = m0 + m;
            int bytes = (node < N_NODES) ? 8 : 0;
            int nd    = (node < N_NODES) ? node : 0;
            cp_async8(sa + (uint32_t)(m * (A_HSTRIDE * 2) + c4 * 2),
                      Asrc + (size_t)nd * FDIM + c0 + c4, bytes);
        }
        {
            const __half* src = g_Bt + (size_t)tid * 384 + col;
            uint32_t d = sb + (uint32_t)(tid * (B_HSTRIDE * 2));
            cp_async16(d, src, 16);
            cp_async16(d + 16, src + 8, 16);
        }
        asm volatile("cp.async.commit_group;" ::: "memory");
    };

    load_stage(0, 0);

    const int ar = lane >> 2;
    const int ac = lane & 3;

    for (int kb = 0; kb < NKB; kb++) {
        int s = kb & 1;
        if (kb + 1 < NKB) {
            load_stage(kb + 1, s ^ 1);
            asm volatile("cp.async.wait_group 1;" ::: "memory");
        } else {
            asm volatile("cp.async.wait_group 0;" ::: "memory");
        }
        __syncthreads();

        const char*   sbase = (const char*)smem + s * STG_BYTES;
        const __half* A  = (const __half*)sbase;
        const __half* Bt = (const __half*)(sbase + A_BYTES);

        const int r0 = mwb + ar;
        uint32_t a[4];
        a[0] = *(const uint32_t*)(A + r0 * A_HSTRIDE + 2 * ac);
        a[1] = *(const uint32_t*)(A + (r0 + 8) * A_HSTRIDE + 2 * ac);
        a[2] = *(const uint32_t*)(A + r0 * A_HSTRIDE + 2 * ac + 8);
        a[3] = *(const uint32_t*)(A + (r0 + 8) * A_HSTRIDE + 2 * ac + 8);

#pragma unroll
        for (int half = 0; half < 2; half++) {
#pragma unroll
            for (int ni = 0; ni < 8; ni++) {
                int n = half * 128 + wn * 64 + ni * 8 + ar;
                uint32_t b[2];
                b[0] = *(const uint32_t*)(Bt + n * B_HSTRIDE + 2 * ac);
                b[1] = *(const uint32_t*)(Bt + n * B_HSTRIDE + 2 * ac + 8);
                mma_f16(c[half * 8 + ni], a, b);
            }
        }
        __syncthreads();
    }

    // ---- epilogue ----
    float* Hn    = smem;
    float* WlinT = smem + BMF * HN_STRIDE;
    for (int idx = tid; idx < TDIM * HDIM; idx += 256) {
        int t = idx % TDIM;
        int h = idx / TDIM;
        WlinT[t * HDIM + h] = Wlin[h * TDIM + t];
    }

    const int mb = mwb + ar;
#pragma unroll
    for (int ni = 0; ni < 8; ni++) {
        int n = wn * 64 + ni * 8 + ac * 2;
        float bz_a = bz0[n] + bz1[n];
        float bz_b = bz0[n + 1] + bz1[n + 1];
        float bh_a = bh0[n] + bh1[n];
        float bh_b = bh0[n + 1] + bh1[n + 1];
        Hn[mb * HN_STRIDE + n]           = gate_fn(c[ni][0] + bz_a, c[8 + ni][0] + bh_a);
        Hn[mb * HN_STRIDE + n + 1]       = gate_fn(c[ni][1] + bz_b, c[8 + ni][1] + bh_b);
        Hn[(mb + 8) * HN_STRIDE + n]     = gate_fn(c[ni][2] + bz_a, c[8 + ni][2] + bh_a);
        Hn[(mb + 8) * HN_STRIDE + n + 1] = gate_fn(c[ni][3] + bz_b, c[8 + ni][3] + bh_b);
    }
    __syncthreads();

    if (tid < 2 * BMF) {
        int m = tid >> 1;
        int g = tid & 1;
        int node = m0 + m;
        if (node < N_NODES) {
            float acc[5];
#pragma unroll
            for (int j = 0; j < 5; j++) acc[j] = blin[g * 5 + j];
            const float* hrow = Hn + m * HN_STRIDE;
#pragma unroll 8
            for (int h = 0; h < HDIM; h++) {
                float v = hrow[h];
#pragma unroll
                for (int j = 0; j < 5; j++)
                    acc[j] += v * WlinT[(g * 5 + j) * HDIM + h];
            }
#pragma unroll
            for (int j = 0; j < 5; j++)
                out[(size_t)node * TDIM + g * 5 + j] = acc[j];
        }
    }
}

// ---------------------------------------------------------------------------
// Launch
// ---------------------------------------------------------------------------
extern "C" void kernel_launch(void* const* d_in, const int* in_sizes, int n_in,
                              void* d_out, int out_size) {
    const float* x    = (const float*)d_in[0];
    const int*   ei   = (const int*)d_in[1];      // int32 (JAX x64 disabled)
    const float* ew   = (const float*)d_in[2];
    const float* Wxz  = (const float*)d_in[3];
    const float* bxz  = (const float*)d_in[4];
    const float* bhz  = (const float*)d_in[6];
    const float* Wxh  = (const float*)d_in[11];
    const float* bxh  = (const float*)d_in[12];
    const float* bhh  = (const float*)d_in[14];
    const float* Wlin = (const float*)d_in[15];
    const float* blin = (const float*)d_in[16];
    float*       out  = (float*)d_out;

    cudaFuncSetAttribute(fused_kernel,
                         cudaFuncAttributeMaxDynamicSharedMemorySize, SMEM_BYTES);

    // Preamble
    split_kernel<<<384, 256>>>(Wxz, Wxh);
    cvtx_kernel<<<(N_NODES * FDIM / 4 + 255) / 256, 256>>>(x);
    deg_kernel<<<(N_EDGES + 255) / 256, 256>>>(ei, ew);
    blocksum_kernel<<<NB, 256>>>();
    blockscan_kernel<<<1, 256>>>();
    rowptr_kernel<<<NB, 256>>>();
    scatter_kernel<<<(N_EDGES + 255) / 256, 256>>>(ei, ew);

    // Gather-side propagation: HALF-WARP per node -> 16 nodes per 256-thr block
    const int PROP_BLOCKS = (N_NODES * 16 + 255) / 256;
    prop1_csr_kernel<<<PROP_BLOCKS, 256>>>();
    prop2_csr_kernel<<<PROP_BLOCKS, 256>>>();

    fused_kernel<<<(N_NODES + BMF - 1) / BMF, 256, SMEM_BYTES>>>(
        bxz, bhz, bxh, bhh, Wlin, blin, out);
}

// round 16
// speedup vs baseline: 1.0326x; 1.0326x over previous
#include <cuda_runtime.h>
#include <cuda_fp16.h>
#include <cstdint>

#define N_NODES 50000
#define N_EDGES 800000
#define FDIM    128
#define HDIM    128
#define TDIM    10
#define NB      ((N_NODES + 255) / 256)    // 196 scan blocks

// Scratch (device globals) — only ever referenced from DEVICE code.
__device__ __align__(16) float g_dinv[N_NODES];
__device__ int  g_cnt[N_NODES];
__device__ int  g_rowptr[N_NODES];
__device__ int  g_cursor[N_NODES];
__device__ int  g_blocksum[NB];
__device__ __align__(16) int2   g_edges[N_EDGES];
// fp16 A-side data path
__device__ __align__(16) __half g_x16[N_NODES * FDIM];
__device__ __align__(16) __half g_T1h[N_NODES * FDIM];
__device__ __align__(16) __half g_T2h[N_NODES * FDIM];   // P = L_hat @ T1
// fp16 B, TRANSPOSED [n=256][k=384], weight-folded:
//   k<128: W0-W2 ; 128<=k<256: W1 ; k>=256: 2*W2   (n<128: z | n>=128: h)
__device__ __align__(16) __half g_Bt[256 * 384];

// ---------------------------------------------------------------------------
// Stage 0: weight fold -> fp16 B^T + init + x->fp16, ONE launch
// grid covers 1.6M threads; first 98304 also do the B fold, first 50000 init.
// ---------------------------------------------------------------------------
__global__ void prep_kernel(const float* __restrict__ Wz,
                            const float* __restrict__ Wh,
                            const float* __restrict__ x) {
    int idx = blockIdx.x * blockDim.x + threadIdx.x;
    if (idx < N_NODES) { g_dinv[idx] = 0.f; g_cnt[idx] = 0; }
    if (idx < 256 * 384) {
        int n = idx / 384;
        int k = idx % 384;
        const float* W = (n < 128) ? Wz : Wh;
        int cc = n & 127;
        float v;
        if (k < 128)      v = W[k * 128 + cc] - W[(k + 256) * 128 + cc];  // W0 - W2
        else if (k < 256) v = W[k * 128 + cc];                            // W1
        else              v = 2.f * W[k * 128 + cc];                      // 2*W2
        g_Bt[idx] = __float2half_rn(v);
    }
    if (idx < N_NODES * FDIM / 4) {
        float4 v = ((const float4*)x)[idx];
        __half2 lo = __floats2half2_rn(v.x, v.y);
        __half2 hi = __floats2half2_rn(v.z, v.w);
        uint2 o;
        o.x = *reinterpret_cast<uint32_t*>(&lo);
        o.y = *reinterpret_cast<uint32_t*>(&hi);
        ((uint2*)g_x16)[idx] = o;
    }
}

// Stage 1: deg[src] += w ; cnt[dst] += 1        (edge_index is int32)
__global__ void deg_kernel(const int* __restrict__ ei,
                           const float* __restrict__ ew) {
    int e = blockIdx.x * blockDim.x + threadIdx.x;
    if (e < N_EDGES) {
        atomicAdd(&g_dinv[ei[e]], ew[e]);
        atomicAdd(&g_cnt[ei[N_EDGES + e]], 1);
    }
}

// ---------------------------------------------------------------------------
// Stage 2a: dinv transform + per-block sums
// ---------------------------------------------------------------------------
__global__ void blocksum_kernel() {
    int i = blockIdx.x * 256 + threadIdx.x;
    int v = 0;
    if (i < N_NODES) {
        v = g_cnt[i];
        float d = g_dinv[i];
        g_dinv[i] = (d > 0.f) ? rsqrtf(d) : 0.f;
    }
    __shared__ int ws[8];
    int lane = threadIdx.x & 31, wid = threadIdx.x >> 5;
#pragma unroll
    for (int o = 16; o > 0; o >>= 1) v += __shfl_down_sync(0xffffffffu, v, o);
    if (lane == 0) ws[wid] = v;
    __syncthreads();
    if (threadIdx.x == 0) {
        int s = 0;
#pragma unroll
        for (int w = 0; w < 8; w++) s += ws[w];
        g_blocksum[blockIdx.x] = s;
    }
}

// ---------------------------------------------------------------------------
// Stage 2b: rowptr — inline block offset (predicated reduce over blocksums)
// + block-internal exclusive scan.  (blockscan kernel eliminated)
// ---------------------------------------------------------------------------
__global__ void rowptr_kernel() {
    const int tid  = threadIdx.x;
    const int lane = tid & 31, wid = tid >> 5;
    __shared__ int ws[8];
    __shared__ int blockoff_s;

    // block offset = sum of blocksum[0..bid)
    int bv = (tid < blockIdx.x) ? g_blocksum[tid] : 0;   // NB=196 < 256
    int rv = bv;
#pragma unroll
    for (int o = 16; o > 0; o >>= 1) rv += __shfl_down_sync(0xffffffffu, rv, o);
    if (lane == 0) ws[wid] = rv;
    __syncthreads();
    if (tid == 0) {
        int s = 0;
#pragma unroll
        for (int w = 0; w < 8; w++) s += ws[w];
        blockoff_s = s;
    }
    __syncthreads();

    // block-internal exclusive scan of cnt
    int i = blockIdx.x * 256 + tid;
    int v = (i < N_NODES) ? g_cnt[i] : 0;
    int inc = v;
#pragma unroll
    for (int o = 1; o < 32; o <<= 1) {
        int t = __shfl_up_sync(0xffffffffu, inc, o);
        if (lane >= o) inc += t;
    }
    __syncthreads();                 // ws reuse barrier
    if (lane == 31) ws[wid] = inc;
    __syncthreads();
    if (wid == 0 && lane < 8) {
        int t = ws[lane];
#pragma unroll
        for (int o = 1; o < 8; o <<= 1) {
            int u = __shfl_up_sync(0xffu, t, o);
            if (lane >= o) t += u;
        }
        ws[lane] = t;
    }
    __syncthreads();
    int excl = inc - v + ((wid > 0) ? ws[wid - 1] : 0) + blockoff_s;
    if (i < N_NODES) { g_rowptr[i] = excl; g_cursor[i] = excl; }
}

// Stage 3: scatter packed (src, norm) into dst-grouped CSR slots
__global__ void scatter_kernel(const int* __restrict__ ei,
                               const float* __restrict__ ew) {
    int e = blockIdx.x * blockDim.x + threadIdx.x;
    if (e < N_EDGES) {
        int s = ei[e];
        int d = ei[N_EDGES + e];
        float nrm = -g_dinv[s] * ew[e] * g_dinv[d];
        int pos = atomicAdd(&g_cursor[d], 1);
        g_edges[pos] = make_int2(s, __float_as_int(nrm));
    }
}

// ---------------------------------------------------------------------------
// Stage 4/5: gather-side propagation (fp16 rows), WARP per dst node (R14
// config — the R15 half-warp variant regressed), unroll x8 for MLP.
// ---------------------------------------------------------------------------
__device__ __forceinline__ void fma_h4(float4& acc, float w, uint2 r) {
    __half2 h0 = *reinterpret_cast<__half2*>(&r.x);
    __half2 h1 = *reinterpret_cast<__half2*>(&r.y);
    float2 f0 = __half22float2(h0);
    float2 f1 = __half22float2(h1);
    acc.x += w * f0.x; acc.y += w * f0.y;
    acc.z += w * f1.x; acc.w += w * f1.y;
}

__device__ __forceinline__ void store_h4(__half* dst, float4 acc) {
    __half2 lo = __floats2half2_rn(acc.x, acc.y);
    __half2 hi = __floats2half2_rn(acc.z, acc.w);
    uint2 o;
    o.x = *reinterpret_cast<uint32_t*>(&lo);
    o.y = *reinterpret_cast<uint32_t*>(&hi);
    *reinterpret_cast<uint2*>(dst) = o;
}

__device__ __forceinline__ float4 prop_gather(const __half* __restrict__ in,
                                              int base, int cnt, int lane) {
    float4 acc = make_float4(0.f, 0.f, 0.f, 0.f);
    int j = 0;
    for (; j + 8 <= cnt; j += 8) {
        int2  e[8];
        uint2 r[8];
#pragma unroll
        for (int u = 0; u < 8; u++) e[u] = g_edges[base + j + u];
#pragma unroll
        for (int u = 0; u < 8; u++)
            r[u] = *(const uint2*)(in + (size_t)e[u].x * FDIM + lane * 4);
#pragma unroll
        for (int u = 0; u < 8; u++)
            fma_h4(acc, __int_as_float(e[u].y), r[u]);
    }
    for (; j < cnt; j++) {
        int2 e0 = g_edges[base + j];
        uint2 r0 = *(const uint2*)(in + (size_t)e0.x * FDIM + lane * 4);
        fma_h4(acc, __int_as_float(e0.y), r0);
    }
    return acc;
}

__global__ void prop1_csr_kernel() {
    int node = (blockIdx.x * blockDim.x + threadIdx.x) >> 5;
    int lane = threadIdx.x & 31;
    if (node >= N_NODES) return;
    float4 acc = prop_gather(g_x16, g_rowptr[node], g_cnt[node], lane);
    store_h4(g_T1h + (size_t)node * FDIM + lane * 4, acc);
}

__global__ void prop2_csr_kernel() {
    int node = (blockIdx.x * blockDim.x + threadIdx.x) >> 5;
    int lane = threadIdx.x & 31;
    if (node >= N_NODES) return;
    float4 acc = prop_gather(g_T1h, g_rowptr[node], g_cnt[node], lane);
    store_h4(g_T2h + (size_t)node * FDIM + lane * 4, acc);
}

// ---------------------------------------------------------------------------
// Stage 6: fused GEMM (pure fp16 MMA m16n8k16, fp32 accum) + gate + proj
//   BM=64, BN=256 (128 z | 128 h), BK=16, 8 warps = 4M x 2N
// ---------------------------------------------------------------------------
#define BMF       64
#define BKT       16
#define NKB       24
#define A_HSTRIDE 20                        // halves per A smem row (40 B)
#define A_BYTES   (BMF * A_HSTRIDE * 2)     // 2560
#define B_HSTRIDE 24                        // halves per B smem row (48 B)
#define B_BYTES   (256 * B_HSTRIDE * 2)     // 12288
#define STG_BYTES (A_BYTES + B_BYTES)       // 14848
#define HN_STRIDE 132
#define EPI_BYTES ((BMF * HN_STRIDE + TDIM * HDIM) * 4)   // 38912
#define SMEM_BYTES ((2 * STG_BYTES) > EPI_BYTES ? (2 * STG_BYTES) : EPI_BYTES)

extern __shared__ float smem[];

__device__ __forceinline__ void cp_async16(uint32_t saddr, const void* g, int bytes) {
    asm volatile("cp.async.cg.shared.global [%0], [%1], 16, %2;"
                 :: "r"(saddr), "l"(g), "r"(bytes) : "memory");
}
__device__ __forceinline__ void cp_async8(uint32_t saddr, const void* g, int bytes) {
    asm volatile("cp.async.ca.shared.global [%0], [%1], 8, %2;"
                 :: "r"(saddr), "l"(g), "r"(bytes) : "memory");
}

__device__ __forceinline__ void mma_f16(float* c, const uint32_t* a, const uint32_t* b) {
    asm volatile(
        "mma.sync.aligned.m16n8k16.row.col.f32.f16.f16.f32 "
        "{%0,%1,%2,%3}, {%4,%5,%6,%7}, {%8,%9}, {%0,%1,%2,%3};"
        : "+f"(c[0]), "+f"(c[1]), "+f"(c[2]), "+f"(c[3])
        : "r"(a[0]), "r"(a[1]), "r"(a[2]), "r"(a[3]),
          "r"(b[0]), "r"(b[1]));
}

__device__ __forceinline__ float gate_fn(float z, float h) {
    float sig = 1.f / (1.f + __expf(-z));
    return (1.f - sig) * tanhf(h);
}

__global__ __launch_bounds__(256, 2) void fused_kernel(
    const float* __restrict__ bz0, const float* __restrict__ bz1,
    const float* __restrict__ bh0, const float* __restrict__ bh1,
    const float* __restrict__ Wlin, const float* __restrict__ blin,
    float* __restrict__ out)
{
    const int tid  = threadIdx.x;
    const int lane = tid & 31;
    const int wid  = tid >> 5;
    const int wm   = wid & 3;          // 4 M-blocks of 16
    const int wn   = wid >> 2;         // 2 N-groups of 64
    const int mwb  = wm * 16;
    const int m0   = blockIdx.x * BMF;

    const uint32_t smem_u32 = (uint32_t)__cvta_generic_to_shared(smem);

    float c[16][4];
#pragma unroll
    for (int ni = 0; ni < 16; ni++)
#pragma unroll
        for (int q = 0; q < 4; q++) c[ni][q] = 0.f;

    auto load_stage = [&](int kb, int s) {
        const int col = kb * BKT;
        const __half* Asrc;
        int c0;
        if (col < 128)      { Asrc = g_x16; c0 = col; }
        else if (col < 256) { Asrc = g_T1h; c0 = col - 128; }
        else                { Asrc = g_T2h; c0 = col - 256; }

        uint32_t sa = smem_u32 + (uint32_t)(s * STG_BYTES);
        uint32_t sb = sa + A_BYTES;

        {
            int m  = tid >> 2;
            int c4 = (tid & 3) * 4;
            int node  = m0 + m;
            int bytes = (node < N_NODES) ? 8 : 0;
            int nd    = (node < N_NODES) ? node : 0;
            cp_async8(sa + (uint32_t)(m * (A_HSTRIDE * 2) + c4 * 2),
                      Asrc + (size_t)nd * FDIM + c0 + c4, bytes);
        }
        {
            const __half* src = g_Bt + (size_t)tid * 384 + col;
            uint32_t d = sb + (uint32_t)(tid * (B_HSTRIDE * 2));
            cp_async16(d, src, 16);
            cp_async16(d + 16, src + 8, 16);
        }
        asm volatile("cp.async.commit_group;" ::: "memory");
    };

    load_stage(0, 0);

    const int ar = lane >> 2;
    const int ac = lane & 3;

    for (int kb = 0; kb < NKB; kb++) {
        int s = kb & 1;
        if (kb + 1 < NKB) {
            load_stage(kb + 1, s ^ 1);
            asm volatile("cp.async.wait_group 1;" ::: "memory");
        } else {
            asm volatile("cp.async.wait_group 0;" ::: "memory");
        }
        __syncthreads();

        const char*   sbase = (const char*)smem + s * STG_BYTES;
        const __half* A  = (const __half*)sbase;
        const __half* Bt = (const __half*)(sbase + A_BYTES);

        const int r0 = mwb + ar;
        uint32_t a[4];
        a[0] = *(const uint32_t*)(A + r0 * A_HSTRIDE + 2 * ac);
        a[1] = *(const uint32_t*)(A + (r0 + 8) * A_HSTRIDE + 2 * ac);
        a[2] = *(const uint32_t*)(A + r0 * A_HSTRIDE + 2 * ac + 8);
        a[3] = *(const uint32_t*)(A + (r0 + 8) * A_HSTRIDE + 2 * ac + 8);

#pragma unroll
        for (int half = 0; half < 2; half++) {
#pragma unroll
            for (int ni = 0; ni < 8; ni++) {
                int n = half * 128 + wn * 64 + ni * 8 + ar;
                uint32_t b[2];
                b[0] = *(const uint32_t*)(Bt + n * B_HSTRIDE + 2 * ac);
                b[1] = *(const uint32_t*)(Bt + n * B_HSTRIDE + 2 * ac + 8);
                mma_f16(c[half * 8 + ni], a, b);
            }
        }
        __syncthreads();
    }

    // ---- epilogue ----
    float* Hn    = smem;
    float* WlinT = smem + BMF * HN_STRIDE;
    for (int idx = tid; idx < TDIM * HDIM; idx += 256) {
        int t = idx % TDIM;
        int h = idx / TDIM;
        WlinT[t * HDIM + h] = Wlin[h * TDIM + t];
    }

    const int mb = mwb + ar;
#pragma unroll
    for (int ni = 0; ni < 8; ni++) {
        int n = wn * 64 + ni * 8 + ac * 2;
        float bz_a = bz0[n] + bz1[n];
        float bz_b = bz0[n + 1] + bz1[n + 1];
        float bh_a = bh0[n] + bh1[n];
        float bh_b = bh0[n + 1] + bh1[n + 1];
        Hn[mb * HN_STRIDE + n]           = gate_fn(c[ni][0] + bz_a, c[8 + ni][0] + bh_a);
        Hn[mb * HN_STRIDE + n + 1]       = gate_fn(c[ni][1] + bz_b, c[8 + ni][1] + bh_b);
        Hn[(mb + 8) * HN_STRIDE + n]     = gate_fn(c[ni][2] + bz_a, c[8 + ni][2] + bh_a);
        Hn[(mb + 8) * HN_STRIDE + n + 1] = gate_fn(c[ni][3] + bz_b, c[8 + ni][3] + bh_b);
    }
    __syncthreads();

    if (tid < 2 * BMF) {
        int m = tid >> 1;
        int g = tid & 1;
        int node = m0 + m;
        if (node < N_NODES) {
            float acc[5];
#pragma unroll
            for (int j = 0; j < 5; j++) acc[j] = blin[g * 5 + j];
            const float* hrow = Hn + m * HN_STRIDE;
#pragma unroll 8
            for (int h = 0; h < HDIM; h++) {
                float v = hrow[h];
#pragma unroll
                for (int j = 0; j < 5; j++)
                    acc[j] += v * WlinT[(g * 5 + j) * HDIM + h];
            }
#pragma unroll
            for (int j = 0; j < 5; j++)
                out[(size_t)node * TDIM + g * 5 + j] = acc[j];
        }
    }
}

// ---------------------------------------------------------------------------
// Launch (8 kernels)
// ---------------------------------------------------------------------------
extern "C" void kernel_launch(void* const* d_in, const int* in_sizes, int n_in,
                              void* d_out, int out_size) {
    const float* x    = (const float*)d_in[0];
    const int*   ei   = (const int*)d_in[1];      // int32 (JAX x64 disabled)
    const float* ew   = (const float*)d_in[2];
    const float* Wxz  = (const float*)d_in[3];
    const float* bxz  = (const float*)d_in[4];
    const float* bhz  = (const float*)d_in[6];
    const float* Wxh  = (const float*)d_in[11];
    const float* bxh  = (const float*)d_in[12];
    const float* bhh  = (const float*)d_in[14];
    const float* Wlin = (const float*)d_in[15];
    const float* blin = (const float*)d_in[16];
    float*       out  = (float*)d_out;

    cudaFuncSetAttribute(fused_kernel,
                         cudaFuncAttributeMaxDynamicSharedMemorySize, SMEM_BYTES);

    // Preamble (fused: prep = fold + init + cvtx)
    prep_kernel<<<(N_NODES * FDIM / 4 + 255) / 256, 256>>>(Wxz, Wxh, x);
    deg_kernel<<<(N_EDGES + 255) / 256, 256>>>(ei, ew);
    blocksum_kernel<<<NB, 256>>>();
    rowptr_kernel<<<NB, 256>>>();            // block offset computed inline
    scatter_kernel<<<(N_EDGES + 255) / 256, 256>>>(ei, ew);

    // Gather-side propagation: warp per node (R14 config), MLP=8
    const int PROP_BLOCKS = (N_NODES * 32 + 255) / 256;
    prop1_csr_kernel<<<PROP_BLOCKS, 256>>>();
    prop2_csr_kernel<<<PROP_BLOCKS, 256>>>();

    fused_kernel<<<(N_NODES + BMF - 1) / BMF, 256, SMEM_BYTES>>>(
        bxz, bhz, bxh, bhh, Wlin, blin, out);
}